// round 12
// baseline (speedup 1.0000x reference)
#include <cuda_runtime.h>

// Problem constants
#define NN 1024
#define DD 64
#define RR 32
#define NEGV (-1e14f)

// Scratch / accumulators (no device allocation allowed).
// Zero-initialized at load; k_stats re-zeroes them after consuming, so every
// kernel_launch call (and every graph replay) starts from the same state.
__device__ float g_ewm[(size_t)NN * NN];
__device__ double g_sum;
__device__ double g_sumsq;
__device__ unsigned long long g_cnt;
__device__ float g_mean;
__device__ float g_invstd;

// ewm[i,j] = sum_d grad[i,j,d] * rs[j,i,d]
// Block = 16x16 pair tile for DRAM locality on the transposed rs reads.
// 8 lanes per pair, float4 loads. 2-deep software pipeline: both pair-groups'
// 8 LDG.128 are issued before any shuffle reduction, doubling per-warp MLP.
__global__ void k_ewm(const float* __restrict__ grad,
                      const float* __restrict__ rs) {
    __shared__ double s_sum[8], s_ss[8];
    __shared__ unsigned int s_cnt[8];

    const int tid  = threadIdx.x;
    const int w    = tid >> 5;
    const int lane = tid & 31;
    const int pg   = lane >> 3;   // pair within warp (0..3)
    const int sub  = lane & 7;    // chunk within pair (0..7)

    const int i0 = blockIdx.y << 4;
    const int j0 = blockIdx.x << 4;

    float ls = 0.0f, lss = 0.0f;
    unsigned int lc = 0u;

    #pragma unroll
    for (int t = 0; t < 8; t += 2) {
        // ---- addresses for both groups ----
        const int gA = t * 8 + w;
        const int gB = gA + 8;
        const int iA  = i0 + (gA >> 2);
        const int jbA = j0 + ((gA & 3) << 2);
        const int iB  = i0 + (gB >> 2);
        const int jbB = j0 + ((gB & 3) << 2);

        const float4* gaA = (const float4*)(grad + (((size_t)iA << 10) + jbA + pg) * DD);
        const float4* raA = (const float4*)(rs   + (((size_t)(jbA + pg) << 10) + iA) * DD);
        const float4* gaB = (const float4*)(grad + (((size_t)iB << 10) + jbB + pg) * DD);
        const float4* raB = (const float4*)(rs   + (((size_t)(jbB + pg) << 10) + iB) * DD);

        // ---- issue all 8 loads up front ----
        float4 Ag0 = gaA[sub];
        float4 Ag1 = gaA[sub + 8];
        float4 Ar0 = raA[sub];
        float4 Ar1 = raA[sub + 8];
        float4 Bg0 = gaB[sub];
        float4 Bg1 = gaB[sub + 8];
        float4 Br0 = raB[sub];
        float4 Br1 = raB[sub + 8];

        // ---- group A ----
        float accA = Ag0.x * Ar0.x + Ag0.y * Ar0.y + Ag0.z * Ar0.z + Ag0.w * Ar0.w
                   + Ag1.x * Ar1.x + Ag1.y * Ar1.y + Ag1.z * Ar1.z + Ag1.w * Ar1.w;
        accA += __shfl_xor_sync(0xffffffffu, accA, 4);
        accA += __shfl_xor_sync(0xffffffffu, accA, 2);
        accA += __shfl_xor_sync(0xffffffffu, accA, 1);

        float a0 = __shfl_sync(0xffffffffu, accA, 0);
        float a1 = __shfl_sync(0xffffffffu, accA, 8);
        float a2 = __shfl_sync(0xffffffffu, accA, 16);
        float a3 = __shfl_sync(0xffffffffu, accA, 24);
        if (lane == 0)
            *(float4*)(g_ewm + ((size_t)iA << 10) + jbA) = make_float4(a0, a1, a2, a3);
        if (sub == 0 && accA != 0.0f) { ls += accA; lss += accA * accA; lc += 1u; }

        // ---- group B ----
        float accB = Bg0.x * Br0.x + Bg0.y * Br0.y + Bg0.z * Br0.z + Bg0.w * Br0.w
                   + Bg1.x * Br1.x + Bg1.y * Br1.y + Bg1.z * Br1.z + Bg1.w * Br1.w;
        accB += __shfl_xor_sync(0xffffffffu, accB, 4);
        accB += __shfl_xor_sync(0xffffffffu, accB, 2);
        accB += __shfl_xor_sync(0xffffffffu, accB, 1);

        float b0 = __shfl_sync(0xffffffffu, accB, 0);
        float b1 = __shfl_sync(0xffffffffu, accB, 8);
        float b2 = __shfl_sync(0xffffffffu, accB, 16);
        float b3 = __shfl_sync(0xffffffffu, accB, 24);
        if (lane == 0)
            *(float4*)(g_ewm + ((size_t)iB << 10) + jbB) = make_float4(b0, b1, b2, b3);
        if (sub == 0 && accB != 0.0f) { ls += accB; lss += accB * accB; lc += 1u; }
    }

    // warp reduce (only lanes with sub==0 carry data; others are zero)
    #pragma unroll
    for (int off = 16; off > 0; off >>= 1) {
        ls  += __shfl_xor_sync(0xffffffffu, ls, off);
        lss += __shfl_xor_sync(0xffffffffu, lss, off);
        lc  += __shfl_xor_sync(0xffffffffu, lc, off);
    }
    if (lane == 0) { s_sum[w] = (double)ls; s_ss[w] = (double)lss; s_cnt[w] = lc; }
    __syncthreads();
    if (tid == 0) {
        double bs = 0.0, bss = 0.0;
        unsigned int bc = 0u;
        #pragma unroll
        for (int k = 0; k < 8; ++k) { bs += s_sum[k]; bss += s_ss[k]; bc += s_cnt[k]; }
        if (bc) {
            atomicAdd(&g_sum, bs);
            atomicAdd(&g_sumsq, bss);
            atomicAdd(&g_cnt, (unsigned long long)bc);
        }
    }
}

// Consumes the accumulators and re-zeroes them for the next replay.
__global__ void k_stats() {
    double c    = (double)g_cnt;
    double mean = g_sum / c;
    double var  = (g_sumsq - g_sum * g_sum / c) / (c - 1.0);
    g_mean   = (float)mean;
    g_invstd = (float)(1.0 / sqrt(var));
    g_sum = 0.0;
    g_sumsq = 0.0;
    g_cnt = 0ull;
}

// Softmax/scale for one 4-value slice of a pair. 8-lane-group reductions.
__device__ __forceinline__ void out_pair(float4 m, float4 mg, float ew,
                                         float mean, float invstd,
                                         float4& o) {
    float4 g = make_float4(m.x * mg.x, m.y * mg.y, m.z * mg.z, m.w * mg.w);

    float mx = fmaxf(fmaxf(g.x, g.y), fmaxf(g.z, g.w));
    float mn = fminf(fminf(g.x, g.y), fminf(g.z, g.w));
    #pragma unroll
    for (int off = 4; off > 0; off >>= 1) {
        mx = fmaxf(mx, __shfl_xor_sync(0xffffffffu, mx, off));
        mn = fminf(mn, __shfl_xor_sync(0xffffffffu, mn, off));
    }

    const float inv2 = 2.0f / (mx - mn);   // inf if all-zero; e's selected to 0 below

    float e0 = (g.x == 0.0f) ? 0.0f : __expf(fmaf(g.x - mn, inv2, -1.0f));
    float e1 = (g.y == 0.0f) ? 0.0f : __expf(fmaf(g.y - mn, inv2, -1.0f));
    float e2 = (g.z == 0.0f) ? 0.0f : __expf(fmaf(g.z - mn, inv2, -1.0f));
    float e3 = (g.w == 0.0f) ? 0.0f : __expf(fmaf(g.w - mn, inv2, -1.0f));

    float s = (e0 + e1) + (e2 + e3);
    #pragma unroll
    for (int off = 4; off > 0; off >>= 1)
        s += __shfl_xor_sync(0xffffffffu, s, off);

    const float invs = (s > 0.0f) ? (1.0f / s) : 0.0f;

    float sig = 0.0f;
    if (ew != 0.0f)
        sig = 1.0f / (1.0f + __expf(-(ew - mean) * invstd));

    const float f = sig * invs;
    o = make_float4(e0 * m.x * f, e1 * m.y * f, e2 * m.z * f, e3 * m.w * f);
}

// Fused epilogue: each warp handles 8 pairs as two independent 512B-contiguous
// float4 sets, loaded back-to-back before compute for doubled MLP.
__global__ void k_out(const float* __restrict__ rm,
                      const float* __restrict__ rmg,
                      float* __restrict__ out) {
    const int lane = threadIdx.x & 31;
    const int pg   = lane >> 3;
    const int W    = (blockIdx.x * blockDim.x + threadIdx.x) >> 5;

    const size_t b0 = (size_t)W * 64 + lane;   // float4 idx, set A (pairs 8W..8W+3)
    const size_t b1 = b0 + 32;                 // set B (pairs 8W+4..8W+7)
    const int pA = W * 8 + pg;
    const int pB = pA + 4;

    // issue all loads first (MLP)
    float4 mA  = __ldcs(((const float4*)rm)  + b0);
    float4 gA  = __ldcs(((const float4*)rmg) + b0);
    float4 mB  = __ldcs(((const float4*)rm)  + b1);
    float4 gB  = __ldcs(((const float4*)rmg) + b1);
    float ewA = g_ewm[pA];
    float ewB = g_ewm[pB];

    const float mean   = g_mean;
    const float invstd = g_invstd;

    float4 oA, oB;
    out_pair(mA, gA, ewA, mean, invstd, oA);
    out_pair(mB, gB, ewB, mean, invstd, oB);

    __stcs(((float4*)out) + b0, oA);
    __stcs(((float4*)out) + b1, oB);
}

extern "C" void kernel_launch(void* const* d_in, const int* in_sizes, int n_in,
                              void* d_out, int out_size) {
    const float* rs   = (const float*)d_in[0];  // relation_stocks [N,N,D]
    const float* grad = (const float*)d_in[1];  // grad            [N,N,D]
    const float* rm   = (const float*)d_in[2];  // relation_matrix [N,N,R]
    const float* rmg  = (const float*)d_in[3];  // relation_matrix_grad [N,N,R]
    float* out = (float*)d_out;                 // [N,N,R]

    (void)in_sizes; (void)n_in; (void)out_size;

    k_ewm<<<dim3(64, 64), 256>>>(grad, rs);
    k_stats<<<1, 1>>>();
    // 1M pairs / (8 pairs/warp * 8 warps/block) = 16384 blocks
    k_out<<<16384, 256>>>(rm, rmg, out);
}

// round 13
// speedup vs baseline: 1.0533x; 1.0533x over previous
#include <cuda_runtime.h>

// Problem constants
#define NN 1024
#define DD 64
#define RR 32
#define NEGV (-1e14f)

// Scratch / accumulators (no device allocation allowed).
// Zero-initialized at load; the last k_ewm block consumes and re-zeroes them,
// so every kernel_launch call (and every graph replay) starts from the same state.
__device__ float g_ewm[(size_t)NN * NN];
__device__ double g_sum;
__device__ double g_sumsq;
__device__ unsigned long long g_cnt;
__device__ unsigned int g_done;
__device__ float g_mean;
__device__ float g_invstd;

// ewm[i,j] = sum_d grad[i,j,d] * rs[j,i,d]
// Block = 16x16 pair tile for DRAM locality on the transposed rs reads.
// 8 lanes per pair, float4 __ldcs loads (evict-first: the 512MB stream must
// not evict the freshly written 4MB g_ewm from L2 — k_out rereads it).
// 2-deep software pipeline: both pair-groups' 8 LDG.128 issued before any
// shuffle reduction. Stats (mean / unbiased std over nonzero ewm) are
// finished by the last block to arrive (ticket pattern) — no separate kernel.
__global__ void k_ewm(const float* __restrict__ grad,
                      const float* __restrict__ rs) {
    __shared__ double s_sum[8], s_ss[8];
    __shared__ unsigned int s_cnt[8];

    const int tid  = threadIdx.x;
    const int w    = tid >> 5;
    const int lane = tid & 31;
    const int pg   = lane >> 3;   // pair within warp (0..3)
    const int sub  = lane & 7;    // chunk within pair (0..7)

    const int i0 = blockIdx.y << 4;
    const int j0 = blockIdx.x << 4;

    float ls = 0.0f, lss = 0.0f;
    unsigned int lc = 0u;

    #pragma unroll
    for (int t = 0; t < 8; t += 2) {
        // ---- addresses for both groups ----
        const int gA = t * 8 + w;
        const int gB = gA + 8;
        const int iA  = i0 + (gA >> 2);
        const int jbA = j0 + ((gA & 3) << 2);
        const int iB  = i0 + (gB >> 2);
        const int jbB = j0 + ((gB & 3) << 2);

        const float4* gaA = (const float4*)(grad + (((size_t)iA << 10) + jbA + pg) * DD);
        const float4* raA = (const float4*)(rs   + (((size_t)(jbA + pg) << 10) + iA) * DD);
        const float4* gaB = (const float4*)(grad + (((size_t)iB << 10) + jbB + pg) * DD);
        const float4* raB = (const float4*)(rs   + (((size_t)(jbB + pg) << 10) + iB) * DD);

        // ---- issue all 8 loads up front (evict-first) ----
        float4 Ag0 = __ldcs(gaA + sub);
        float4 Ag1 = __ldcs(gaA + sub + 8);
        float4 Ar0 = __ldcs(raA + sub);
        float4 Ar1 = __ldcs(raA + sub + 8);
        float4 Bg0 = __ldcs(gaB + sub);
        float4 Bg1 = __ldcs(gaB + sub + 8);
        float4 Br0 = __ldcs(raB + sub);
        float4 Br1 = __ldcs(raB + sub + 8);

        // ---- group A ----
        float accA = Ag0.x * Ar0.x + Ag0.y * Ar0.y + Ag0.z * Ar0.z + Ag0.w * Ar0.w
                   + Ag1.x * Ar1.x + Ag1.y * Ar1.y + Ag1.z * Ar1.z + Ag1.w * Ar1.w;
        accA += __shfl_xor_sync(0xffffffffu, accA, 4);
        accA += __shfl_xor_sync(0xffffffffu, accA, 2);
        accA += __shfl_xor_sync(0xffffffffu, accA, 1);

        float a0 = __shfl_sync(0xffffffffu, accA, 0);
        float a1 = __shfl_sync(0xffffffffu, accA, 8);
        float a2 = __shfl_sync(0xffffffffu, accA, 16);
        float a3 = __shfl_sync(0xffffffffu, accA, 24);
        if (lane == 0)
            *(float4*)(g_ewm + ((size_t)iA << 10) + jbA) = make_float4(a0, a1, a2, a3);
        if (sub == 0 && accA != 0.0f) { ls += accA; lss += accA * accA; lc += 1u; }

        // ---- group B ----
        float accB = Bg0.x * Br0.x + Bg0.y * Br0.y + Bg0.z * Br0.z + Bg0.w * Br0.w
                   + Bg1.x * Br1.x + Bg1.y * Br1.y + Bg1.z * Br1.z + Bg1.w * Br1.w;
        accB += __shfl_xor_sync(0xffffffffu, accB, 4);
        accB += __shfl_xor_sync(0xffffffffu, accB, 2);
        accB += __shfl_xor_sync(0xffffffffu, accB, 1);

        float b0 = __shfl_sync(0xffffffffu, accB, 0);
        float b1 = __shfl_sync(0xffffffffu, accB, 8);
        float b2 = __shfl_sync(0xffffffffu, accB, 16);
        float b3 = __shfl_sync(0xffffffffu, accB, 24);
        if (lane == 0)
            *(float4*)(g_ewm + ((size_t)iB << 10) + jbB) = make_float4(b0, b1, b2, b3);
        if (sub == 0 && accB != 0.0f) { ls += accB; lss += accB * accB; lc += 1u; }
    }

    // warp reduce (only lanes with sub==0 carry data; others are zero)
    #pragma unroll
    for (int off = 16; off > 0; off >>= 1) {
        ls  += __shfl_xor_sync(0xffffffffu, ls, off);
        lss += __shfl_xor_sync(0xffffffffu, lss, off);
        lc  += __shfl_xor_sync(0xffffffffu, lc, off);
    }
    if (lane == 0) { s_sum[w] = (double)ls; s_ss[w] = (double)lss; s_cnt[w] = lc; }
    __syncthreads();
    if (tid == 0) {
        double bs = 0.0, bss = 0.0;
        unsigned int bc = 0u;
        #pragma unroll
        for (int k = 0; k < 8; ++k) { bs += s_sum[k]; bss += s_ss[k]; bc += s_cnt[k]; }
        if (bc) {
            atomicAdd(&g_sum, bs);
            atomicAdd(&g_sumsq, bss);
            atomicAdd(&g_cnt, (unsigned long long)bc);
        }
        __threadfence();
        const unsigned int total = gridDim.x * gridDim.y;
        unsigned int ticket = atomicAdd(&g_done, 1u);
        if (ticket == total - 1) {
            // all blocks' accumulator updates are visible now
            double c    = (double)g_cnt;
            double mean = g_sum / c;
            double var  = (g_sumsq - g_sum * g_sum / c) / (c - 1.0);
            g_mean   = (float)mean;
            g_invstd = (float)(1.0 / sqrt(var));
            // reset for the next graph replay
            g_sum = 0.0;
            g_sumsq = 0.0;
            g_cnt = 0ull;
            g_done = 0u;
            __threadfence();
        }
    }
}

// Softmax/scale for one 4-value slice of a pair. 8-lane-group reductions.
__device__ __forceinline__ void out_pair(float4 m, float4 mg, float ew,
                                         float mean, float invstd,
                                         float4& o) {
    float4 g = make_float4(m.x * mg.x, m.y * mg.y, m.z * mg.z, m.w * mg.w);

    float mx = fmaxf(fmaxf(g.x, g.y), fmaxf(g.z, g.w));
    float mn = fminf(fminf(g.x, g.y), fminf(g.z, g.w));
    #pragma unroll
    for (int off = 4; off > 0; off >>= 1) {
        mx = fmaxf(mx, __shfl_xor_sync(0xffffffffu, mx, off));
        mn = fminf(mn, __shfl_xor_sync(0xffffffffu, mn, off));
    }

    const float inv2 = 2.0f / (mx - mn);   // inf if all-zero; e's selected to 0 below

    float e0 = (g.x == 0.0f) ? 0.0f : __expf(fmaf(g.x - mn, inv2, -1.0f));
    float e1 = (g.y == 0.0f) ? 0.0f : __expf(fmaf(g.y - mn, inv2, -1.0f));
    float e2 = (g.z == 0.0f) ? 0.0f : __expf(fmaf(g.z - mn, inv2, -1.0f));
    float e3 = (g.w == 0.0f) ? 0.0f : __expf(fmaf(g.w - mn, inv2, -1.0f));

    float s = (e0 + e1) + (e2 + e3);
    #pragma unroll
    for (int off = 4; off > 0; off >>= 1)
        s += __shfl_xor_sync(0xffffffffu, s, off);

    const float invs = (s > 0.0f) ? (1.0f / s) : 0.0f;

    float sig = 0.0f;
    if (ew != 0.0f)
        sig = 1.0f / (1.0f + __expf(-(ew - mean) * invstd));

    const float f = sig * invs;
    o = make_float4(e0 * m.x * f, e1 * m.y * f, e2 * m.z * f, e3 * m.w * f);
}

// Fused epilogue: each warp handles 8 pairs as two independent 512B-contiguous
// float4 sets, loaded back-to-back before compute for doubled MLP. The g_ewm
// (possibly-L2-miss) loads are issued first to overlap with the rm/rmg stream.
__global__ void k_out(const float* __restrict__ rm,
                      const float* __restrict__ rmg,
                      float* __restrict__ out) {
    const int lane = threadIdx.x & 31;
    const int pg   = lane >> 3;
    const int W    = (blockIdx.x * blockDim.x + threadIdx.x) >> 5;

    const size_t b0 = (size_t)W * 64 + lane;   // float4 idx, set A (pairs 8W..8W+3)
    const size_t b1 = b0 + 32;                 // set B (pairs 8W+4..8W+7)
    const int pA = W * 8 + pg;
    const int pB = pA + 4;

    // issue all loads first (MLP); ewm first to hide any L2 miss
    float ewA = g_ewm[pA];
    float ewB = g_ewm[pB];
    float4 mA  = __ldcs(((const float4*)rm)  + b0);
    float4 gA  = __ldcs(((const float4*)rmg) + b0);
    float4 mB  = __ldcs(((const float4*)rm)  + b1);
    float4 gB  = __ldcs(((const float4*)rmg) + b1);

    const float mean   = g_mean;
    const float invstd = g_invstd;

    float4 oA, oB;
    out_pair(mA, gA, ewA, mean, invstd, oA);
    out_pair(mB, gB, ewB, mean, invstd, oB);

    __stcs(((float4*)out) + b0, oA);
    __stcs(((float4*)out) + b1, oB);
}

extern "C" void kernel_launch(void* const* d_in, const int* in_sizes, int n_in,
                              void* d_out, int out_size) {
    const float* rs   = (const float*)d_in[0];  // relation_stocks [N,N,D]
    const float* grad = (const float*)d_in[1];  // grad            [N,N,D]
    const float* rm   = (const float*)d_in[2];  // relation_matrix [N,N,R]
    const float* rmg  = (const float*)d_in[3];  // relation_matrix_grad [N,N,R]
    float* out = (float*)d_out;                 // [N,N,R]

    (void)in_sizes; (void)n_in; (void)out_size;

    k_ewm<<<dim3(64, 64), 256>>>(grad, rs);
    // 1M pairs / (8 pairs/warp * 8 warps/block) = 16384 blocks
    k_out<<<16384, 256>>>(rm, rmg, out);
}